// round 4
// baseline (speedup 1.0000x reference)
#include <cuda_runtime.h>
#include <cuda_bf16.h>
#include <math.h>
#include <stdint.h>

// ---------------- problem constants ----------------
#define Bz 32
#define TE 2048
#define TDd 64
#define Dd 1024
#define Mrows (Bz * TE)      // 65536

// ---------------- scratch (device globals) ----------------
__device__ __nv_bfloat16 g_Bhi[(size_t)Dd * Dd];      // W^T hi : [n][k]
__device__ __nv_bfloat16 g_Blo[(size_t)Dd * Dd];      // W^T lo : [n][k]
__device__ float g_dU[Bz * Dd];
__device__ float g_scores[Bz * TE];
__device__ float g_weights[Bz * TE];

// ---------------- helpers ----------------
__device__ __forceinline__ uint32_t smem_to_u32(const void* p) {
    uint32_t a;
    asm("{ .reg .u64 t; cvta.to.shared.u64 t, %1; cvt.u32.u64 %0, t; }" : "=r"(a) : "l"(p));
    return a;
}
__device__ __forceinline__ void cp16(uint32_t s, const void* g) {
    asm volatile("cp.async.cg.shared.global [%0], [%1], 16;" :: "r"(s), "l"(g));
}
#define CP_COMMIT() asm volatile("cp.async.commit_group;" ::: "memory")
#define CP_WAIT(n)  asm volatile("cp.async.wait_group %0;" :: "n"(n) : "memory")
#define LDSM_X4(r0, r1, r2, r3, addr) \
    asm volatile("ldmatrix.sync.aligned.m8n8.x4.shared.b16 {%0,%1,%2,%3}, [%4];" \
        : "=r"(r0), "=r"(r1), "=r"(r2), "=r"(r3) : "r"(addr))
#define MMA16816(d0, d1, d2, d3, a0, a1, a2, a3, b0, b1) \
    asm volatile("mma.sync.aligned.m16n8k16.row.col.f32.bf16.bf16.f32 " \
        "{%0,%1,%2,%3}, {%4,%5,%6,%7}, {%8,%9}, {%0,%1,%2,%3};" \
        : "+f"(d0), "+f"(d1), "+f"(d2), "+f"(d3) \
        : "r"(a0), "r"(a1), "r"(a2), "r"(a3), "r"(b0), "r"(b1))

__device__ __forceinline__ uint32_t sw128(uint32_t off) {
    return off ^ ((off >> 3) & 0x70);
}

// ---------------- GEMM tiling ----------------
#define BM 128
#define BN 128
#define BKE 64                        // k elements per chunk (128 B bf16 rows)
#define NKC 16                        // 16 k-chunks of 64
#define SM_AHI 0
#define SM_ALO 16384
#define SM_B   32768                  // + stage*32768 ; Bhi at +0, Blo at +16384
#define SMEM_TOTAL (32768 + 2 * 32768)   // 96 KB

// ---------------- conversion / setup kernels ----------------
__global__ void convert_W_kernel(const float* __restrict__ W) {
    int id = blockIdx.x * 256 + threadIdx.x;
    int n = id >> 10, k = id & 1023;
    float v = W[(size_t)k * Dd + n];           // transpose -> [n][k]
    __nv_bfloat16 h = __float2bfloat16(v);
    g_Bhi[(size_t)n * Dd + k] = h;
    g_Blo[(size_t)n * Dd + k] = __float2bfloat16(v - __bfloat162float(h));
}

__global__ void zero_kernel() {
    int i = blockIdx.x * blockDim.x + threadIdx.x;
    if (i < Bz * TE) g_scores[i] = 0.0f;
    if (i < Bz * Dd) g_dU[i] = 0.0f;
}

// dU[b][f] = sum_k dec_last[b][k] * U[k][f]
// grid (Dd/256, 8) : block x -> 256 f values, block y -> 128-k split
__global__ void dU_kernel(const float* __restrict__ dec, const float* __restrict__ U) {
    const int f  = blockIdx.x * 256 + threadIdx.x;
    const int k0 = blockIdx.y * 128;
    __shared__ float sdec[Bz][128];
#pragma unroll
    for (int j = 0; j < 16; j++) {
        int idx = threadIdx.x + j * 256;
        int b = idx >> 7, kk = idx & 127;
        sdec[b][kk] = dec[((size_t)b * TDd + (TDd - 1)) * Dd + k0 + kk];
    }
    __syncthreads();
    float acc[Bz];
#pragma unroll
    for (int b = 0; b < Bz; b++) acc[b] = 0.0f;
    for (int kk = 0; kk < 128; kk++) {
        float u = U[(size_t)(k0 + kk) * Dd + f];
#pragma unroll
        for (int b = 0; b < Bz; b++) acc[b] = fmaf(u, sdec[b][kk], acc[b]);
    }
#pragma unroll
    for (int b = 0; b < Bz; b++) atomicAdd(&g_dU[b * Dd + f], acc[b]);
}

// ---------------- fused GEMM + epilogue ----------------
__device__ __forceinline__ void loadB(uint32_t sbase, int stage, int kc,
                                      int nbase, int tid) {
    uint32_t sBh = sbase + SM_B + stage * 32768;
    uint32_t sBl = sBh + 16384;
    const int kb = kc * BKE;
#pragma unroll
    for (int i = 0; i < 4; i++) {
        int u = tid + i * 256;                 // 0..1023
        int r = u >> 3, ch = u & 7;
        uint32_t off = sw128((uint32_t)(r * 128 + ch * 16));
        const size_t gofs = (size_t)(nbase + r) * Dd + kb + ch * 8;
        cp16(sBh + off, g_Bhi + gofs);
        cp16(sBl + off, g_Blo + gofs);
    }
    CP_COMMIT();
}

__device__ __forceinline__ void loadA_regs(const float* __restrict__ enc,
                                           float4 (&areg)[8], int mbase, int kc, int tid) {
    const int kb = kc * BKE;
#pragma unroll
    for (int i = 0; i < 8; i++) {
        int u = tid + i * 256;                 // 0..2047
        int r = u >> 4, c4 = u & 15;
        areg[i] = *(const float4*)(enc + (size_t)(mbase + r) * Dd + kb + c4 * 4);
    }
}

__device__ __forceinline__ void storeA_smem(char* smem, const float4 (&areg)[8], int tid) {
#pragma unroll
    for (int i = 0; i < 8; i++) {
        int u = tid + i * 256;
        int r = u >> 4, c4 = u & 15;
        uint32_t off = sw128((uint32_t)(r * 128 + c4 * 8));
        float4 v = areg[i];
        __nv_bfloat162 h0 = __floats2bfloat162_rn(v.x, v.y);
        __nv_bfloat162 h1 = __floats2bfloat162_rn(v.z, v.w);
        uint2 hp; hp.x = *(uint32_t*)&h0; hp.y = *(uint32_t*)&h1;
        *(uint2*)(smem + SM_AHI + off) = hp;
        __nv_bfloat162 l0 = __floats2bfloat162_rn(v.x - __bfloat162float(h0.x),
                                                  v.y - __bfloat162float(h0.y));
        __nv_bfloat162 l1 = __floats2bfloat162_rn(v.z - __bfloat162float(h1.x),
                                                  v.w - __bfloat162float(h1.y));
        uint2 lp; lp.x = *(uint32_t*)&l0; lp.y = *(uint32_t*)&l1;
        *(uint2*)(smem + SM_ALO + off) = lp;
    }
}

__global__ void __launch_bounds__(256, 2) gemm_score_fused(const float* __restrict__ enc,
                                                           const float* __restrict__ V) {
    extern __shared__ char smem[];
    uint32_t sbase = smem_to_u32(smem);

    const int tid  = threadIdx.x;
    const int wid  = tid >> 5;
    const int lane = tid & 31;
    const int wm   = wid >> 2;      // 0..1
    const int wn   = wid & 3;       // 0..3

    const int nblk  = blockIdx.x & 7;
    const int mblk  = blockIdx.x >> 3;
    const int mbase = mblk * BM;
    const int nbase = nblk * BN;
    const int b     = mbase >> 11;

    float acc[4][4][4];
#pragma unroll
    for (int mt = 0; mt < 4; mt++)
#pragma unroll
        for (int nt = 0; nt < 4; nt++)
#pragma unroll
            for (int i = 0; i < 4; i++) acc[mt][nt][i] = 0.0f;

    const int a_r  = lane & 15;
    const int a_kc = lane >> 4;
    const int b_n  = ((lane >> 4) & 1) * 8 + (lane & 7);
    const int b_kc = (lane >> 3) & 1;

    // prologue: B(0) async, A(0) -> regs -> smem
    loadB(sbase, 0, 0, nbase, tid);
    float4 areg[8];
    loadA_regs(enc, areg, mbase, 0, tid);
    storeA_smem(smem, areg, tid);

    for (int kc = 0; kc < NKC; kc++) {
        const int stage = kc & 1;
        if (kc + 1 < NKC) {
            loadB(sbase, stage ^ 1, kc + 1, nbase, tid);
            CP_WAIT(1);
        } else {
            CP_WAIT(0);
        }
        __syncthreads();   // B(kc) ready in smem; A(kc) stored; safe to read

        if (kc + 1 < NKC) loadA_regs(enc, areg, mbase, kc + 1, tid);

        const uint32_t sAh = sbase + SM_AHI;
        const uint32_t sAl = sbase + SM_ALO;
        const uint32_t sBh = sbase + SM_B + stage * 32768;
        const uint32_t sBl = sBh + 16384;

#pragma unroll
        for (int ks = 0; ks < 4; ks++) {
            uint32_t bh[2][4], bl[2][4];
#pragma unroll
            for (int p = 0; p < 2; p++) {
                int row = wn * 32 + p * 16 + b_n;
                uint32_t off = sw128((uint32_t)(row * 128 + (ks * 2 + b_kc) * 16));
                LDSM_X4(bh[p][0], bh[p][1], bh[p][2], bh[p][3], sBh + off);
                LDSM_X4(bl[p][0], bl[p][1], bl[p][2], bl[p][3], sBl + off);
            }
            uint32_t af[4][4];
#pragma unroll
            for (int mt = 0; mt < 4; mt++) {
                int row = wm * 64 + mt * 16 + a_r;
                uint32_t off = sw128((uint32_t)(row * 128 + (ks * 2 + a_kc) * 16));
                LDSM_X4(af[mt][0], af[mt][1], af[mt][2], af[mt][3], sAh + off);
            }
            // Ahi * Bhi  and  Ahi * Blo
#pragma unroll
            for (int mt = 0; mt < 4; mt++)
#pragma unroll
                for (int nt = 0; nt < 4; nt++) {
                    MMA16816(acc[mt][nt][0], acc[mt][nt][1], acc[mt][nt][2], acc[mt][nt][3],
                             af[mt][0], af[mt][1], af[mt][2], af[mt][3],
                             bh[nt >> 1][(nt & 1) * 2], bh[nt >> 1][(nt & 1) * 2 + 1]);
                    MMA16816(acc[mt][nt][0], acc[mt][nt][1], acc[mt][nt][2], acc[mt][nt][3],
                             af[mt][0], af[mt][1], af[mt][2], af[mt][3],
                             bl[nt >> 1][(nt & 1) * 2], bl[nt >> 1][(nt & 1) * 2 + 1]);
                }
            // Alo * Bhi (reuse af regs)
#pragma unroll
            for (int mt = 0; mt < 4; mt++) {
                int row = wm * 64 + mt * 16 + a_r;
                uint32_t off = sw128((uint32_t)(row * 128 + (ks * 2 + a_kc) * 16));
                LDSM_X4(af[mt][0], af[mt][1], af[mt][2], af[mt][3], sAl + off);
            }
#pragma unroll
            for (int mt = 0; mt < 4; mt++)
#pragma unroll
                for (int nt = 0; nt < 4; nt++)
                    MMA16816(acc[mt][nt][0], acc[mt][nt][1], acc[mt][nt][2], acc[mt][nt][3],
                             af[mt][0], af[mt][1], af[mt][2], af[mt][3],
                             bh[nt >> 1][(nt & 1) * 2], bh[nt >> 1][(nt & 1) * 2 + 1]);
        }
        __syncthreads();   // all reads of sA(kc) done
        if (kc + 1 < NKC) storeA_smem(smem, areg, tid);
    }

    // ---- fused epilogue ----
    const int q = lane >> 2;
    const int t4 = lane & 3;
#pragma unroll
    for (int mt = 0; mt < 4; mt++) {
        float s0 = 0.0f, s1 = 0.0f;
#pragma unroll
        for (int nt = 0; nt < 4; nt++) {
            int n0 = nbase + wn * 32 + nt * 8 + 2 * t4;
            float v0 = V[n0], v1 = V[n0 + 1];
            float u0 = g_dU[b * Dd + n0], u1 = g_dU[b * Dd + n0 + 1];
            s0 = fmaf(v0, tanhf(acc[mt][nt][0] + u0), s0);
            s0 = fmaf(v1, tanhf(acc[mt][nt][1] + u1), s0);
            s1 = fmaf(v0, tanhf(acc[mt][nt][2] + u0), s1);
            s1 = fmaf(v1, tanhf(acc[mt][nt][3] + u1), s1);
        }
        s0 += __shfl_xor_sync(0xFFFFFFFF, s0, 1);
        s0 += __shfl_xor_sync(0xFFFFFFFF, s0, 2);
        s1 += __shfl_xor_sync(0xFFFFFFFF, s1, 1);
        s1 += __shfl_xor_sync(0xFFFFFFFF, s1, 2);
        if (t4 == 0) {
            int row = mbase + wm * 64 + mt * 16 + q;
            atomicAdd(&g_scores[row], s0);
            atomicAdd(&g_scores[row + 8], s1);
        }
    }
}

// ---------------- softmax & context ----------------
__global__ void softmax_kernel(float* __restrict__ out_weights) {
    const int b = blockIdx.x;
    const int tid = threadIdx.x;
    __shared__ float red[256];
    float local[8];
    float mx = -INFINITY;
#pragma unroll
    for (int i = 0; i < 8; i++) {
        local[i] = g_scores[b * TE + tid + i * 256];
        mx = fmaxf(mx, local[i]);
    }
    red[tid] = mx;
    __syncthreads();
    for (int s = 128; s > 0; s >>= 1) {
        if (tid < s) red[tid] = fmaxf(red[tid], red[tid + s]);
        __syncthreads();
    }
    mx = red[0];
    __syncthreads();
    float sum = 0.0f;
#pragma unroll
    for (int i = 0; i < 8; i++) { local[i] = expf(local[i] - mx); sum += local[i]; }
    red[tid] = sum;
    __syncthreads();
    for (int s = 128; s > 0; s >>= 1) {
        if (tid < s) red[tid] += red[tid + s];
        __syncthreads();
    }
    const float inv = 1.0f / red[0];
#pragma unroll
    for (int i = 0; i < 8; i++) {
        float w = local[i] * inv;
        g_weights[b * TE + tid + i * 256]   = w;
        out_weights[b * TE + tid + i * 256] = w;
    }
}

__global__ void context_kernel(const float* __restrict__ enc, float* __restrict__ out_context) {
    const int b = blockIdx.x;
    const int e = blockIdx.y * 256 + threadIdx.x;
    __shared__ float sw[TE];
    for (int i = threadIdx.x; i < TE; i += 256) sw[i] = g_weights[b * TE + i];
    __syncthreads();
    const float* base = enc + (size_t)b * TE * Dd + e;
    float acc = 0.0f;
#pragma unroll 8
    for (int t = 0; t < TE; t++) acc = fmaf(sw[t], base[(size_t)t * Dd], acc);
    out_context[b * Dd + e] = acc;
}

// ---------------- launch ----------------
extern "C" void kernel_launch(void* const* d_in, const int* in_sizes, int n_in,
                              void* d_out, int out_size) {
    const float* enc = (const float*)d_in[0];
    const float* dec = (const float*)d_in[1];
    const float* W_a = (const float*)d_in[2];
    const float* U_a = (const float*)d_in[3];
    const float* V_a = (const float*)d_in[4];
    float* out = (float*)d_out;
    float* out_context = out;            // 32*1024
    float* out_weights = out + Bz * Dd;  // 32*2048

    static int smem_set = 0;
    if (!smem_set) {
        cudaFuncSetAttribute(gemm_score_fused, cudaFuncAttributeMaxDynamicSharedMemorySize, SMEM_TOTAL);
        smem_set = 1;
    }

    convert_W_kernel<<<(Dd * Dd) / 256, 256>>>(W_a);
    zero_kernel<<<(Bz * TE + 255) / 256, 256>>>();
    {
        dim3 g(Dd / 256, 8);
        dU_kernel<<<g, 256>>>(dec, U_a);
    }
    gemm_score_fused<<<(Mrows / BM) * (Dd / BN), 256, SMEM_TOTAL>>>(enc, V_a);
    softmax_kernel<<<Bz, 256>>>(out_weights);
    {
        dim3 g(Bz, Dd / 256);
        context_kernel<<<g, 256>>>(enc, out_context);
    }
}

// round 5
// speedup vs baseline: 1.0045x; 1.0045x over previous
#include <cuda_runtime.h>
#include <cuda_bf16.h>
#include <math.h>
#include <stdint.h>

// ---------------- problem constants ----------------
#define Bz 32
#define TE 2048
#define TDd 64
#define Dd 1024
#define Mrows (Bz * TE)      // 65536

// ---------------- scratch (device globals) ----------------
__device__ __nv_bfloat16 g_Bhi[(size_t)Dd * Dd];      // W^T hi : [n][k]
__device__ __nv_bfloat16 g_Blo[(size_t)Dd * Dd];      // W^T lo : [n][k]
__device__ float g_dU[Bz * Dd];
__device__ float g_scores[Bz * TE];
__device__ float g_weights[Bz * TE];

// ---------------- helpers ----------------
__device__ __forceinline__ uint32_t smem_to_u32(const void* p) {
    uint32_t a;
    asm("{ .reg .u64 t; cvta.to.shared.u64 t, %1; cvt.u32.u64 %0, t; }" : "=r"(a) : "l"(p));
    return a;
}
__device__ __forceinline__ void cp16(uint32_t s, const void* g) {
    asm volatile("cp.async.cg.shared.global [%0], [%1], 16;" :: "r"(s), "l"(g));
}
#define CP_COMMIT() asm volatile("cp.async.commit_group;" ::: "memory")
#define CP_WAIT(n)  asm volatile("cp.async.wait_group %0;" :: "n"(n) : "memory")
#define LDSM_X4(r0, r1, r2, r3, addr) \
    asm volatile("ldmatrix.sync.aligned.m8n8.x4.shared.b16 {%0,%1,%2,%3}, [%4];" \
        : "=r"(r0), "=r"(r1), "=r"(r2), "=r"(r3) : "r"(addr))
#define MMA16816(d0, d1, d2, d3, a0, a1, a2, a3, b0, b1) \
    asm volatile("mma.sync.aligned.m16n8k16.row.col.f32.bf16.bf16.f32 " \
        "{%0,%1,%2,%3}, {%4,%5,%6,%7}, {%8,%9}, {%0,%1,%2,%3};" \
        : "+f"(d0), "+f"(d1), "+f"(d2), "+f"(d3) \
        : "r"(a0), "r"(a1), "r"(a2), "r"(a3), "r"(b0), "r"(b1))

__device__ __forceinline__ uint32_t sw128(uint32_t off) {
    return off ^ ((off >> 3) & 0x70);
}

// ---------------- GEMM tiling ----------------
#define BM 128
#define BN 128
#define BKE 64                        // k elements per chunk (128 B bf16 rows)
#define NKC 16                        // 16 k-chunks of 64
#define SM_AHI 0
#define SM_ALO 16384
#define SM_B   32768                  // + stage*32768 ; Bhi at +0, Blo at +16384
#define SMEM_TOTAL (32768 + 2 * 32768)   // 96 KB

// ---------------- setup kernels ----------------
__global__ void convert_W_kernel(const float* __restrict__ W) {
    int id = blockIdx.x * 256 + threadIdx.x;
    int n = id >> 10, k = id & 1023;
    float v = W[(size_t)k * Dd + n];           // transpose -> [n][k]
    __nv_bfloat16 h = __float2bfloat16(v);
    g_Bhi[(size_t)n * Dd + k] = h;
    g_Blo[(size_t)n * Dd + k] = __float2bfloat16(v - __bfloat162float(h));
}

__global__ void zero_kernel() {
    int i = blockIdx.x * blockDim.x + threadIdx.x;
    if (i < Bz * TE) g_scores[i] = 0.0f;
    if (i < Bz * Dd) g_dU[i] = 0.0f;
}

// dU[b][f] = sum_k dec_last[b][k] * U[k][f]
__global__ void dU_kernel(const float* __restrict__ dec, const float* __restrict__ U) {
    const int f  = blockIdx.x * 256 + threadIdx.x;
    const int k0 = blockIdx.y * 128;
    __shared__ float sdec[Bz][128];
#pragma unroll
    for (int j = 0; j < 16; j++) {
        int idx = threadIdx.x + j * 256;
        int b = idx >> 7, kk = idx & 127;
        sdec[b][kk] = dec[((size_t)b * TDd + (TDd - 1)) * Dd + k0 + kk];
    }
    __syncthreads();
    float acc[Bz];
#pragma unroll
    for (int b = 0; b < Bz; b++) acc[b] = 0.0f;
    for (int kk = 0; kk < 128; kk++) {
        float u = U[(size_t)(k0 + kk) * Dd + f];
#pragma unroll
        for (int b = 0; b < Bz; b++) acc[b] = fmaf(u, sdec[b][kk], acc[b]);
    }
#pragma unroll
    for (int b = 0; b < Bz; b++) atomicAdd(&g_dU[b * Dd + f], acc[b]);
}

// ---------------- fused GEMM + epilogue ----------------
__device__ __forceinline__ void loadB(uint32_t sbase, int stage, int kc,
                                      int nbase, int tid) {
    uint32_t sBh = sbase + SM_B + stage * 32768;
    uint32_t sBl = sBh + 16384;
    const int kb = kc * BKE;
#pragma unroll
    for (int i = 0; i < 4; i++) {
        int u = tid + i * 256;                 // 0..1023
        int r = u >> 3, ch = u & 7;
        uint32_t off = sw128((uint32_t)(r * 128 + ch * 16));
        const size_t gofs = (size_t)(nbase + r) * Dd + kb + ch * 8;
        cp16(sBh + off, g_Bhi + gofs);
        cp16(sBl + off, g_Blo + gofs);
    }
    CP_COMMIT();
}

__device__ __forceinline__ void loadA_regs(const float* __restrict__ enc,
                                           float4 (&areg)[8], int mbase, int kc, int tid) {
    const int kb = kc * BKE;
#pragma unroll
    for (int i = 0; i < 8; i++) {
        int u = tid + i * 256;                 // 0..2047
        int r = u >> 4, c4 = u & 15;
        areg[i] = *(const float4*)(enc + (size_t)(mbase + r) * Dd + kb + c4 * 4);
    }
}

__device__ __forceinline__ void storeA_smem(char* smem, const float4 (&areg)[8], int tid) {
#pragma unroll
    for (int i = 0; i < 8; i++) {
        int u = tid + i * 256;
        int r = u >> 4, c4 = u & 15;
        uint32_t off = sw128((uint32_t)(r * 128 + c4 * 8));
        float4 v = areg[i];
        __nv_bfloat162 h0 = __floats2bfloat162_rn(v.x, v.y);
        __nv_bfloat162 h1 = __floats2bfloat162_rn(v.z, v.w);
        uint2 hp; hp.x = *(uint32_t*)&h0; hp.y = *(uint32_t*)&h1;
        *(uint2*)(smem + SM_AHI + off) = hp;
        __nv_bfloat162 l0 = __floats2bfloat162_rn(v.x - __bfloat162float(h0.x),
                                                  v.y - __bfloat162float(h0.y));
        __nv_bfloat162 l1 = __floats2bfloat162_rn(v.z - __bfloat162float(h1.x),
                                                  v.w - __bfloat162float(h1.y));
        uint2 lp; lp.x = *(uint32_t*)&l0; lp.y = *(uint32_t*)&l1;
        *(uint2*)(smem + SM_ALO + off) = lp;
    }
}

__global__ void __launch_bounds__(256, 2) gemm_score_fused(const float* __restrict__ enc,
                                                           const float* __restrict__ V) {
    extern __shared__ char smem[];
    uint32_t sbase = smem_to_u32(smem);

    const int tid  = threadIdx.x;
    const int wid  = tid >> 5;
    const int lane = tid & 31;
    const int wm   = wid >> 2;      // 0..1
    const int wn   = wid & 3;       // 0..3

    const int nblk  = blockIdx.x & 7;
    const int mblk  = blockIdx.x >> 3;
    const int mbase = mblk * BM;
    const int nbase = nblk * BN;
    const int b     = mbase >> 11;

    float acc[4][4][4];
#pragma unroll
    for (int mt = 0; mt < 4; mt++)
#pragma unroll
        for (int nt = 0; nt < 4; nt++)
#pragma unroll
            for (int i = 0; i < 4; i++) acc[mt][nt][i] = 0.0f;

    const int a_r  = lane & 15;
    const int a_kc = lane >> 4;
    const int b_n  = ((lane >> 4) & 1) * 8 + (lane & 7);
    const int b_kc = (lane >> 3) & 1;

    // prologue
    loadB(sbase, 0, 0, nbase, tid);
    float4 areg[8];
    loadA_regs(enc, areg, mbase, 0, tid);
    storeA_smem(smem, areg, tid);

    for (int kc = 0; kc < NKC; kc++) {
        const int stage = kc & 1;
        if (kc + 1 < NKC) {
            loadB(sbase, stage ^ 1, kc + 1, nbase, tid);
            CP_WAIT(1);
        } else {
            CP_WAIT(0);
        }
        __syncthreads();   // B(kc) in smem; A(kc) stored

        if (kc + 1 < NKC) loadA_regs(enc, areg, mbase, kc + 1, tid);

        const uint32_t sAh = sbase + SM_AHI;
        const uint32_t sAl = sbase + SM_ALO;
        const uint32_t sBh = sbase + SM_B + stage * 32768;
        const uint32_t sBl = sBh + 16384;

#pragma unroll
        for (int ks = 0; ks < 4; ks++) {
            uint32_t bh[2][4], bl[2][4], af[4][4];
#pragma unroll
            for (int p = 0; p < 2; p++) {
                int row = wn * 32 + p * 16 + b_n;
                uint32_t off = sw128((uint32_t)(row * 128 + (ks * 2 + b_kc) * 16));
                LDSM_X4(bh[p][0], bh[p][1], bh[p][2], bh[p][3], sBh + off);
                LDSM_X4(bl[p][0], bl[p][1], bl[p][2], bl[p][3], sBl + off);
            }
#pragma unroll
            for (int mt = 0; mt < 4; mt++) {
                int row = wm * 64 + mt * 16 + a_r;
                uint32_t off = sw128((uint32_t)(row * 128 + (ks * 2 + a_kc) * 16));
                LDSM_X4(af[mt][0], af[mt][1], af[mt][2], af[mt][3], sAh + off);
            }
            // pass 1: Ahi * Bhi  (16 independent MMAs)
#pragma unroll
            for (int mt = 0; mt < 4; mt++)
#pragma unroll
                for (int nt = 0; nt < 4; nt++)
                    MMA16816(acc[mt][nt][0], acc[mt][nt][1], acc[mt][nt][2], acc[mt][nt][3],
                             af[mt][0], af[mt][1], af[mt][2], af[mt][3],
                             bh[nt >> 1][(nt & 1) * 2], bh[nt >> 1][(nt & 1) * 2 + 1]);
            // pass 2: Ahi * Blo  (16 independent MMAs)
#pragma unroll
            for (int mt = 0; mt < 4; mt++)
#pragma unroll
                for (int nt = 0; nt < 4; nt++)
                    MMA16816(acc[mt][nt][0], acc[mt][nt][1], acc[mt][nt][2], acc[mt][nt][3],
                             af[mt][0], af[mt][1], af[mt][2], af[mt][3],
                             bl[nt >> 1][(nt & 1) * 2], bl[nt >> 1][(nt & 1) * 2 + 1]);
            // reload A (lo) — WAR on af handled by scoreboard
#pragma unroll
            for (int mt = 0; mt < 4; mt++) {
                int row = wm * 64 + mt * 16 + a_r;
                uint32_t off = sw128((uint32_t)(row * 128 + (ks * 2 + a_kc) * 16));
                LDSM_X4(af[mt][0], af[mt][1], af[mt][2], af[mt][3], sAl + off);
            }
            // pass 3: Alo * Bhi  (16 independent MMAs)
#pragma unroll
            for (int mt = 0; mt < 4; mt++)
#pragma unroll
                for (int nt = 0; nt < 4; nt++)
                    MMA16816(acc[mt][nt][0], acc[mt][nt][1], acc[mt][nt][2], acc[mt][nt][3],
                             af[mt][0], af[mt][1], af[mt][2], af[mt][3],
                             bh[nt >> 1][(nt & 1) * 2], bh[nt >> 1][(nt & 1) * 2 + 1]);
        }
        __syncthreads();   // all reads of sA(kc) done
        if (kc + 1 < NKC) storeA_smem(smem, areg, tid);
    }

    // ---- fused epilogue ----
    const int q = lane >> 2;
    const int t4 = lane & 3;
#pragma unroll
    for (int mt = 0; mt < 4; mt++) {
        float s0 = 0.0f, s1 = 0.0f;
#pragma unroll
        for (int nt = 0; nt < 4; nt++) {
            int n0 = nbase + wn * 32 + nt * 8 + 2 * t4;
            float v0 = V[n0], v1 = V[n0 + 1];
            float u0 = g_dU[b * Dd + n0], u1 = g_dU[b * Dd + n0 + 1];
            s0 = fmaf(v0, tanhf(acc[mt][nt][0] + u0), s0);
            s0 = fmaf(v1, tanhf(acc[mt][nt][1] + u1), s0);
            s1 = fmaf(v0, tanhf(acc[mt][nt][2] + u0), s1);
            s1 = fmaf(v1, tanhf(acc[mt][nt][3] + u1), s1);
        }
        s0 += __shfl_xor_sync(0xFFFFFFFF, s0, 1);
        s0 += __shfl_xor_sync(0xFFFFFFFF, s0, 2);
        s1 += __shfl_xor_sync(0xFFFFFFFF, s1, 1);
        s1 += __shfl_xor_sync(0xFFFFFFFF, s1, 2);
        if (t4 == 0) {
            int row = mbase + wm * 64 + mt * 16 + q;
            atomicAdd(&g_scores[row], s0);
            atomicAdd(&g_scores[row + 8], s1);
        }
    }
}

// ---------------- softmax & context ----------------
__global__ void softmax_kernel(float* __restrict__ out_weights) {
    const int b = blockIdx.x;
    const int tid = threadIdx.x;
    __shared__ float red[256];
    float local[8];
    float mx = -INFINITY;
#pragma unroll
    for (int i = 0; i < 8; i++) {
        local[i] = g_scores[b * TE + tid + i * 256];
        mx = fmaxf(mx, local[i]);
    }
    red[tid] = mx;
    __syncthreads();
    for (int s = 128; s > 0; s >>= 1) {
        if (tid < s) red[tid] = fmaxf(red[tid], red[tid + s]);
        __syncthreads();
    }
    mx = red[0];
    __syncthreads();
    float sum = 0.0f;
#pragma unroll
    for (int i = 0; i < 8; i++) { local[i] = expf(local[i] - mx); sum += local[i]; }
    red[tid] = sum;
    __syncthreads();
    for (int s = 128; s > 0; s >>= 1) {
        if (tid < s) red[tid] += red[tid + s];
        __syncthreads();
    }
    const float inv = 1.0f / red[0];
#pragma unroll
    for (int i = 0; i < 8; i++) {
        float w = local[i] * inv;
        g_weights[b * TE + tid + i * 256]   = w;
        out_weights[b * TE + tid + i * 256] = w;
    }
}

__global__ void context_kernel(const float* __restrict__ enc, float* __restrict__ out_context) {
    const int b = blockIdx.x;
    const int e = blockIdx.y * 256 + threadIdx.x;
    __shared__ float sw[TE];
    for (int i = threadIdx.x; i < TE; i += 256) sw[i] = g_weights[b * TE + i];
    __syncthreads();
    const float* base = enc + (size_t)b * TE * Dd + e;
    float acc = 0.0f;
#pragma unroll 8
    for (int t = 0; t < TE; t++) acc = fmaf(sw[t], base[(size_t)t * Dd], acc);
    out_context[b * Dd + e] = acc;
}

// ---------------- launch ----------------
extern "C" void kernel_launch(void* const* d_in, const int* in_sizes, int n_in,
                              void* d_out, int out_size) {
    const float* enc = (const float*)d_in[0];
    const float* dec = (const float*)d_in[1];
    const float* W_a = (const float*)d_in[2];
    const float* U_a = (const float*)d_in[3];
    const float* V_a = (const float*)d_in[4];
    float* out = (float*)d_out;
    float* out_context = out;            // 32*1024
    float* out_weights = out + Bz * Dd;  // 32*2048

    static int smem_set = 0;
    if (!smem_set) {
        cudaFuncSetAttribute(gemm_score_fused, cudaFuncAttributeMaxDynamicSharedMemorySize, SMEM_TOTAL);
        smem_set = 1;
    }

    convert_W_kernel<<<(Dd * Dd) / 256, 256>>>(W_a);
    zero_kernel<<<(Bz * TE + 255) / 256, 256>>>();
    {
        dim3 g(Dd / 256, 8);
        dU_kernel<<<g, 256>>>(dec, U_a);
    }
    gemm_score_fused<<<(Mrows / BM) * (Dd / BN), 256, SMEM_TOTAL>>>(enc, V_a);
    softmax_kernel<<<Bz, 256>>>(out_weights);
    {
        dim3 g(Bz, Dd / 256);
        context_kernel<<<g, 256>>>(enc, out_context);
    }
}

// round 6
// speedup vs baseline: 1.1123x; 1.1072x over previous
#include <cuda_runtime.h>
#include <cuda_bf16.h>
#include <math.h>
#include <stdint.h>

// ---------------- problem constants ----------------
#define Bz 32
#define TE 2048
#define TDd 64
#define Dd 1024
#define Mrows (Bz * TE)      // 65536

// ---------------- scratch (device globals) ----------------
__device__ __nv_bfloat16 g_Ahi[(size_t)Mrows * Dd];
__device__ __nv_bfloat16 g_Alo[(size_t)Mrows * Dd];
__device__ __nv_bfloat16 g_Bhi[(size_t)Dd * Dd];      // W^T hi : [n][k]
__device__ __nv_bfloat16 g_Blo[(size_t)Dd * Dd];      // W^T lo : [n][k]
__device__ float g_dU[Bz * Dd];
__device__ float g_scores[Bz * TE];
__device__ float g_weights[Bz * TE];

// ---------------- helpers ----------------
__device__ __forceinline__ uint32_t smem_to_u32(const void* p) {
    uint32_t a;
    asm("{ .reg .u64 t; cvta.to.shared.u64 t, %1; cvt.u32.u64 %0, t; }" : "=r"(a) : "l"(p));
    return a;
}
__device__ __forceinline__ void cp16(uint32_t s, const void* g) {
    asm volatile("cp.async.cg.shared.global [%0], [%1], 16;" :: "r"(s), "l"(g));
}
#define CP_COMMIT() asm volatile("cp.async.commit_group;" ::: "memory")
#define CP_WAIT(n)  asm volatile("cp.async.wait_group %0;" :: "n"(n) : "memory")
#define LDSM_X4(r0, r1, r2, r3, addr) \
    asm volatile("ldmatrix.sync.aligned.m8n8.x4.shared.b16 {%0,%1,%2,%3}, [%4];" \
        : "=r"(r0), "=r"(r1), "=r"(r2), "=r"(r3) : "r"(addr))
#define MMA16816(d0, d1, d2, d3, a0, a1, a2, a3, b0, b1) \
    asm volatile("mma.sync.aligned.m16n8k16.row.col.f32.bf16.bf16.f32 " \
        "{%0,%1,%2,%3}, {%4,%5,%6,%7}, {%8,%9}, {%0,%1,%2,%3};" \
        : "+f"(d0), "+f"(d1), "+f"(d2), "+f"(d3) \
        : "r"(a0), "r"(a1), "r"(a2), "r"(a3), "r"(b0), "r"(b1))

__device__ __forceinline__ uint32_t sw128(uint32_t off) {
    return off ^ ((off >> 3) & 0x70);
}

// ---------------- GEMM tiling ----------------
#define BM 128
#define BN 128
#define BKE 64                      // bf16 k per chunk (128 B rows)
#define NKC3 48                     // 3 split phases * 16 k-chunks
#define STG_B 32768                 // per-stage bytes: A 16K + B 16K
#define SMEM_TOTAL (3 * STG_B)      // 96 KB

// ---------------- setup kernels ----------------
// 8 floats per thread
__global__ void convert_A_kernel(const float* __restrict__ enc) {
    size_t i = ((size_t)blockIdx.x * blockDim.x + threadIdx.x) * 8;
    float4 v0 = *(const float4*)(enc + i);
    float4 v1 = *(const float4*)(enc + i + 4);
    __nv_bfloat162 h[4];
    h[0] = __floats2bfloat162_rn(v0.x, v0.y);
    h[1] = __floats2bfloat162_rn(v0.z, v0.w);
    h[2] = __floats2bfloat162_rn(v1.x, v1.y);
    h[3] = __floats2bfloat162_rn(v1.z, v1.w);
    *(uint4*)(g_Ahi + i) = *(uint4*)h;
    __nv_bfloat162 l[4];
    l[0] = __floats2bfloat162_rn(v0.x - __bfloat162float(h[0].x), v0.y - __bfloat162float(h[0].y));
    l[1] = __floats2bfloat162_rn(v0.z - __bfloat162float(h[1].x), v0.w - __bfloat162float(h[1].y));
    l[2] = __floats2bfloat162_rn(v1.x - __bfloat162float(h[2].x), v1.y - __bfloat162float(h[2].y));
    l[3] = __floats2bfloat162_rn(v1.z - __bfloat162float(h[3].x), v1.w - __bfloat162float(h[3].y));
    *(uint4*)(g_Alo + i) = *(uint4*)l;
}

__global__ void convert_W_kernel(const float* __restrict__ W) {
    int id = blockIdx.x * 256 + threadIdx.x;
    int n = id >> 10, k = id & 1023;
    float v = W[(size_t)k * Dd + n];           // transpose -> [n][k]
    __nv_bfloat16 h = __float2bfloat16(v);
    g_Bhi[(size_t)n * Dd + k] = h;
    g_Blo[(size_t)n * Dd + k] = __float2bfloat16(v - __bfloat162float(h));
}

__global__ void zero_kernel() {
    int i = blockIdx.x * blockDim.x + threadIdx.x;
    if (i < Bz * TE) g_scores[i] = 0.0f;
    if (i < Bz * Dd) g_dU[i] = 0.0f;
}

// dU[b][f] = sum_k dec_last[b][k] * U[k][f]
__global__ void dU_kernel(const float* __restrict__ dec, const float* __restrict__ U) {
    const int f  = blockIdx.x * 256 + threadIdx.x;
    const int k0 = blockIdx.y * 128;
    __shared__ float sdec[Bz][128];
#pragma unroll
    for (int j = 0; j < 16; j++) {
        int idx = threadIdx.x + j * 256;
        int b = idx >> 7, kk = idx & 127;
        sdec[b][kk] = dec[((size_t)b * TDd + (TDd - 1)) * Dd + k0 + kk];
    }
    __syncthreads();
    float acc[Bz];
#pragma unroll
    for (int b = 0; b < Bz; b++) acc[b] = 0.0f;
    for (int kk = 0; kk < 128; kk++) {
        float u = U[(size_t)(k0 + kk) * Dd + f];
#pragma unroll
        for (int b = 0; b < Bz; b++) acc[b] = fmaf(u, sdec[b][kk], acc[b]);
    }
#pragma unroll
    for (int b = 0; b < Bz; b++) atomicAdd(&g_dU[b * Dd + f], acc[b]);
}

// ---------------- fused GEMM + epilogue ----------------
__device__ __forceinline__ void load_chunk3(uint32_t sbase, int stage, int c,
                                            int mbase, int nbase, int tid) {
    const int phase = c >> 4;
    const int kb = (c & 15) * BKE;
    const __nv_bfloat16* Ap = (phase < 2) ? g_Ahi : g_Alo;
    const __nv_bfloat16* Bp = (phase == 1) ? g_Blo : g_Bhi;
    uint32_t sA = sbase + stage * STG_B;
    uint32_t sB = sA + 16384;
#pragma unroll
    for (int i = 0; i < 4; i++) {
        int u = tid + i * 256;                 // 0..1023
        int r = u >> 3, ch = u & 7;
        uint32_t off = sw128((uint32_t)(r * 128 + ch * 16));
        cp16(sA + off, Ap + (size_t)(mbase + r) * Dd + kb + ch * 8);
        cp16(sB + off, Bp + (size_t)(nbase + r) * Dd + kb + ch * 8);
    }
    CP_COMMIT();
}

__global__ void __launch_bounds__(256, 2) gemm_score_mma(const float* __restrict__ V) {
    extern __shared__ char smem[];
    uint32_t sbase = smem_to_u32(smem);

    const int tid  = threadIdx.x;
    const int wid  = tid >> 5;
    const int lane = tid & 31;
    const int wm   = wid >> 2;      // 0..1
    const int wn   = wid & 3;       // 0..3

    const int nblk  = blockIdx.x & 7;
    const int mblk  = blockIdx.x >> 3;
    const int mbase = mblk * BM;
    const int nbase = nblk * BN;
    const int b     = mbase >> 11;

    float acc[4][4][4];
#pragma unroll
    for (int mt = 0; mt < 4; mt++)
#pragma unroll
        for (int nt = 0; nt < 4; nt++)
#pragma unroll
            for (int i = 0; i < 4; i++) acc[mt][nt][i] = 0.0f;

    const int a_r  = lane & 15;
    const int a_kc = lane >> 4;
    const int b_n  = ((lane >> 4) & 1) * 8 + (lane & 7);
    const int b_kc = (lane >> 3) & 1;

    // prologue: stages 0,1
    load_chunk3(sbase, 0, 0, mbase, nbase, tid);
    load_chunk3(sbase, 1, 1, mbase, nbase, tid);

    int stage = 0;
    for (int c = 0; c < NKC3; c++) {
        if (c + 2 < NKC3) { CP_WAIT(1); } else { CP_WAIT(0); }
        __syncthreads();                      // chunk c visible; compute(c-1) done by all
        if (c + 2 < NKC3) {
            int ns = stage + 2; if (ns >= 3) ns -= 3;
            load_chunk3(sbase, ns, c + 2, mbase, nbase, tid);
        }

        const uint32_t sA = sbase + stage * STG_B;
        const uint32_t sB = sA + 16384;
#pragma unroll
        for (int ks = 0; ks < 4; ks++) {
            uint32_t af[4][4], bf[2][4];
#pragma unroll
            for (int mt = 0; mt < 4; mt++) {
                int row = wm * 64 + mt * 16 + a_r;
                uint32_t off = sw128((uint32_t)(row * 128 + (ks * 2 + a_kc) * 16));
                LDSM_X4(af[mt][0], af[mt][1], af[mt][2], af[mt][3], sA + off);
            }
#pragma unroll
            for (int p = 0; p < 2; p++) {
                int row = wn * 32 + p * 16 + b_n;
                uint32_t off = sw128((uint32_t)(row * 128 + (ks * 2 + b_kc) * 16));
                LDSM_X4(bf[p][0], bf[p][1], bf[p][2], bf[p][3], sB + off);
            }
#pragma unroll
            for (int mt = 0; mt < 4; mt++)
#pragma unroll
                for (int nt = 0; nt < 4; nt++)
                    MMA16816(acc[mt][nt][0], acc[mt][nt][1], acc[mt][nt][2], acc[mt][nt][3],
                             af[mt][0], af[mt][1], af[mt][2], af[mt][3],
                             bf[nt >> 1][(nt & 1) * 2], bf[nt >> 1][(nt & 1) * 2 + 1]);
        }
        stage++; if (stage >= 3) stage = 0;
    }

    // ---- fused epilogue: scores[m] += sum_n V[n]*tanh(C[m][n] + dU[b][n]) ----
    const int q = lane >> 2;
    const int t4 = lane & 3;
#pragma unroll
    for (int mt = 0; mt < 4; mt++) {
        float s0 = 0.0f, s1 = 0.0f;
#pragma unroll
        for (int nt = 0; nt < 4; nt++) {
            int n0 = nbase + wn * 32 + nt * 8 + 2 * t4;
            float v0 = V[n0], v1 = V[n0 + 1];
            float u0 = g_dU[b * Dd + n0], u1 = g_dU[b * Dd + n0 + 1];
            s0 = fmaf(v0, tanhf(acc[mt][nt][0] + u0), s0);
            s0 = fmaf(v1, tanhf(acc[mt][nt][1] + u1), s0);
            s1 = fmaf(v0, tanhf(acc[mt][nt][2] + u0), s1);
            s1 = fmaf(v1, tanhf(acc[mt][nt][3] + u1), s1);
        }
        s0 += __shfl_xor_sync(0xFFFFFFFF, s0, 1);
        s0 += __shfl_xor_sync(0xFFFFFFFF, s0, 2);
        s1 += __shfl_xor_sync(0xFFFFFFFF, s1, 1);
        s1 += __shfl_xor_sync(0xFFFFFFFF, s1, 2);
        if (t4 == 0) {
            int row = mbase + wm * 64 + mt * 16 + q;
            atomicAdd(&g_scores[row], s0);
            atomicAdd(&g_scores[row + 8], s1);
        }
    }
}

// ---------------- softmax & context ----------------
__global__ void softmax_kernel(float* __restrict__ out_weights) {
    const int b = blockIdx.x;
    const int tid = threadIdx.x;
    __shared__ float red[256];
    float local[8];
    float mx = -INFINITY;
#pragma unroll
    for (int i = 0; i < 8; i++) {
        local[i] = g_scores[b * TE + tid + i * 256];
        mx = fmaxf(mx, local[i]);
    }
    red[tid] = mx;
    __syncthreads();
    for (int s = 128; s > 0; s >>= 1) {
        if (tid < s) red[tid] = fmaxf(red[tid], red[tid + s]);
        __syncthreads();
    }
    mx = red[0];
    __syncthreads();
    float sum = 0.0f;
#pragma unroll
    for (int i = 0; i < 8; i++) { local[i] = expf(local[i] - mx); sum += local[i]; }
    red[tid] = sum;
    __syncthreads();
    for (int s = 128; s > 0; s >>= 1) {
        if (tid < s) red[tid] += red[tid + s];
        __syncthreads();
    }
    const float inv = 1.0f / red[0];
#pragma unroll
    for (int i = 0; i < 8; i++) {
        float w = local[i] * inv;
        g_weights[b * TE + tid + i * 256]   = w;
        out_weights[b * TE + tid + i * 256] = w;
    }
}

__global__ void context_kernel(const float* __restrict__ enc, float* __restrict__ out_context) {
    const int b = blockIdx.x;
    const int e = blockIdx.y * 256 + threadIdx.x;
    __shared__ float sw[TE];
    for (int i = threadIdx.x; i < TE; i += 256) sw[i] = g_weights[b * TE + i];
    __syncthreads();
    const float* base = enc + (size_t)b * TE * Dd + e;
    float acc = 0.0f;
#pragma unroll 8
    for (int t = 0; t < TE; t++) acc = fmaf(sw[t], base[(size_t)t * Dd], acc);
    out_context[b * Dd + e] = acc;
}

// ---------------- launch ----------------
extern "C" void kernel_launch(void* const* d_in, const int* in_sizes, int n_in,
                              void* d_out, int out_size) {
    const float* enc = (const float*)d_in[0];
    const float* dec = (const float*)d_in[1];
    const float* W_a = (const float*)d_in[2];
    const float* U_a = (const float*)d_in[3];
    const float* V_a = (const float*)d_in[4];
    float* out = (float*)d_out;
    float* out_context = out;            // 32*1024
    float* out_weights = out + Bz * Dd;  // 32*2048

    static int smem_set = 0;
    if (!smem_set) {
        cudaFuncSetAttribute(gemm_score_mma, cudaFuncAttributeMaxDynamicSharedMemorySize, SMEM_TOTAL);
        smem_set = 1;
    }

    convert_A_kernel<<<(Mrows * (Dd / 8)) / 256, 256>>>(enc);
    convert_W_kernel<<<(Dd * Dd) / 256, 256>>>(W_a);
    zero_kernel<<<(Bz * TE + 255) / 256, 256>>>();
    {
        dim3 g(Dd / 256, 8);
        dU_kernel<<<g, 256>>>(dec, U_a);
    }
    gemm_score_mma<<<(Mrows / BM) * (Dd / BN), 256, SMEM_TOTAL>>>(V_a);
    softmax_kernel<<<Bz, 256>>>(out_weights);
    {
        dim3 g(Bz, Dd / 256);
        context_kernel<<<g, 256>>>(enc, out_context);
    }
}